// round 2
// baseline (speedup 1.0000x reference)
#include <cuda_runtime.h>

#define DIM 64
#define NPL 16384
#define CPN 8
#define LEVELS 8
#define N_NODES (LEVELS * NPL)
#define EDGES_PER_LEVEL (NPL * CPN)
#define ROWS_PER_BLOCK 32
#define THREADS 256
#define WSTRIDE 68  // 64 + 4 pad: keeps float4 alignment, breaks STS bank conflicts

// out[row] = x[row] @ Wr^T   for all N_NODES rows
__global__ __launch_bounds__(THREADS) void gemm_wr_kernel(
    const float* __restrict__ x,
    const float* __restrict__ Wr,
    float* __restrict__ out)
{
    __shared__ float sWt[DIM * WSTRIDE];          // sWt[k][j] = Wr[j][k]
    __shared__ float sX[ROWS_PER_BLOCK * DIM];

    const int tid = threadIdx.x;

    // Load W coalesced from gmem, transpose into padded smem
#pragma unroll
    for (int i = 0; i < (DIM * DIM) / THREADS; ++i) {
        int idx = tid + i * THREADS;
        int j = idx >> 6;       // output col
        int k = idx & 63;       // input dim
        sWt[k * WSTRIDE + j] = Wr[idx];
    }

    // Load x tile (32 rows x 64) coalesced as float4
    const int rowbase = blockIdx.x * ROWS_PER_BLOCK;
    const float4* xg = (const float4*)(x + (size_t)rowbase * DIM);
    float4* sx4 = (float4*)sX;
#pragma unroll
    for (int i = 0; i < (ROWS_PER_BLOCK * DIM / 4) / THREADS; ++i)
        sx4[tid + i * THREADS] = xg[tid + i * THREADS];

    __syncthreads();

    const int r  = tid >> 3;            // row within block (0..31)
    const int jg = (tid & 7) << 3;      // output col group (0,8,..,56)
    const float* xr = &sX[r * DIM];

    float a0 = 0.f, a1 = 0.f, a2 = 0.f, a3 = 0.f;
    float a4 = 0.f, a5 = 0.f, a6 = 0.f, a7 = 0.f;
#pragma unroll
    for (int k = 0; k < DIM; ++k) {
        float xv = xr[k];
        float4 w0 = *(const float4*)&sWt[k * WSTRIDE + jg];
        float4 w1 = *(const float4*)&sWt[k * WSTRIDE + jg + 4];
        a0 += xv * w0.x; a1 += xv * w0.y; a2 += xv * w0.z; a3 += xv * w0.w;
        a4 += xv * w1.x; a5 += xv * w1.y; a6 += xv * w1.z; a7 += xv * w1.w;
    }

    float* o = out + (size_t)(rowbase + r) * DIM + jg;
    ((float4*)o)[0] = make_float4(a0, a1, a2, a3);
    ((float4*)o)[1] = make_float4(a4, a5, a6, a7);
}

// For level lvl (1..7): out[p] = tanh(out[p] + (sum of 8 children out rows) @ Wl^T + bl)
__global__ __launch_bounds__(THREADS) void level_kernel(
    const int* __restrict__ srcs,
    const int* __restrict__ dsts,
    const float* __restrict__ Wl,
    const float* __restrict__ bl,
    float* __restrict__ out,
    int lvl)
{
    __shared__ float sWt[DIM * WSTRIDE];
    __shared__ float sAgg[ROWS_PER_BLOCK * DIM];
    __shared__ float sB[DIM];

    const int tid = threadIdx.x;

#pragma unroll
    for (int i = 0; i < (DIM * DIM) / THREADS; ++i) {
        int idx = tid + i * THREADS;
        int j = idx >> 6;
        int k = idx & 63;
        sWt[k * WSTRIDE + j] = Wl[idx];
    }
    if (tid < DIM) sB[tid] = bl[tid];

    const int r = tid >> 3;          // parent within block
    const int t = tid & 7;           // lane group within parent
    const int p_local = blockIdx.x * ROWS_PER_BLOCK + r;
    const int eb = (lvl - 1) * EDGES_PER_LEVEL + p_local * CPN;
    const int p_node = dsts[eb];     // parent node id (same for all 8 edges)

    // Gather-sum 8 children rows: this thread handles dims [t*8, t*8+8)
    float g0 = 0.f, g1 = 0.f, g2 = 0.f, g3 = 0.f;
    float g4 = 0.f, g5 = 0.f, g6 = 0.f, g7 = 0.f;
#pragma unroll
    for (int j = 0; j < CPN; ++j) {
        int s = srcs[eb + j];
        const float4* c = (const float4*)(out + (size_t)s * DIM + t * 8);
        float4 c0 = c[0];
        float4 c1 = c[1];
        g0 += c0.x; g1 += c0.y; g2 += c0.z; g3 += c0.w;
        g4 += c1.x; g5 += c1.y; g6 += c1.z; g7 += c1.w;
    }
    float4* sa = (float4*)&sAgg[r * DIM + t * 8];
    sa[0] = make_float4(g0, g1, g2, g3);
    sa[1] = make_float4(g4, g5, g6, g7);

    __syncthreads();

    const int jg = t << 3;
    const float* ag = &sAgg[r * DIM];
    float a0 = 0.f, a1 = 0.f, a2 = 0.f, a3 = 0.f;
    float a4 = 0.f, a5 = 0.f, a6 = 0.f, a7 = 0.f;
#pragma unroll
    for (int k = 0; k < DIM; ++k) {
        float av = ag[k];
        float4 w0 = *(const float4*)&sWt[k * WSTRIDE + jg];
        float4 w1 = *(const float4*)&sWt[k * WSTRIDE + jg + 4];
        a0 += av * w0.x; a1 += av * w0.y; a2 += av * w0.z; a3 += av * w0.w;
        a4 += av * w1.x; a5 += av * w1.y; a6 += av * w1.z; a7 += av * w1.w;
    }

    // Epilogue: tanh(H + agg@Wl^T + b)
    float* o = out + (size_t)p_node * DIM + jg;
    float4 h0 = ((const float4*)o)[0];
    float4 h1 = ((const float4*)o)[1];
    float4 b0 = *(const float4*)&sB[jg];
    float4 b1 = *(const float4*)&sB[jg + 4];

    float4 r0, r1;
    r0.x = tanhf(h0.x + b0.x + a0);
    r0.y = tanhf(h0.y + b0.y + a1);
    r0.z = tanhf(h0.z + b0.z + a2);
    r0.w = tanhf(h0.w + b0.w + a3);
    r1.x = tanhf(h1.x + b1.x + a4);
    r1.y = tanhf(h1.y + b1.y + a5);
    r1.z = tanhf(h1.z + b1.z + a6);
    r1.w = tanhf(h1.w + b1.w + a7);

    ((float4*)o)[0] = r0;
    ((float4*)o)[1] = r1;
}

extern "C" void kernel_launch(void* const* d_in, const int* in_sizes, int n_in,
                              void* d_out, int out_size)
{
    const float* x  = (const float*)d_in[0];
    const int*   ei = (const int*)d_in[1];
    const float* Wl = (const float*)d_in[2];
    const float* bl = (const float*)d_in[3];
    const float* Wr = (const float*)d_in[4];
    float* out = (float*)d_out;

    const int E = in_sizes[1] / 2;
    const int* srcs = ei;
    const int* dsts = ei + E;

    // Step 1: out = x @ Wr^T for all nodes (leaves final; upper levels hold H)
    gemm_wr_kernel<<<N_NODES / ROWS_PER_BLOCK, THREADS>>>(x, Wr, out);

    // Steps 2..8: level-by-level propagation (separate launches = grid sync)
    for (int lvl = 1; lvl < LEVELS; ++lvl)
        level_kernel<<<NPL / ROWS_PER_BLOCK, THREADS>>>(srcs, dsts, Wl, bl, out, lvl);
}

// round 3
// speedup vs baseline: 1.1741x; 1.1741x over previous
#include <cuda_runtime.h>

#define DIM 64
#define NPL 16384
#define CPN 8
#define LEVELS 8
#define N_NODES (LEVELS * NPL)
#define EPL (NPL * CPN)

#define TPB 128          // 4 warps
#define RPB 64           // rows per block; thread = 4 rows x 8 cols
#define XSTR 68          // activation row stride: 68 mod 32 = 4 -> conflict-free for rows差1

// ---------------------------------------------------------------------------
// Shared inner GEMV: acc[4][8] += sAct(4 rows) @ sW^T(8 cols)
// Row mapping: warp w handles rows [w*16, w*16+16); lane: t=lane&7 (col group
// jg=t*8), q=lane>>3; thread's rows are q + 4*i (i=0..3) -> simultaneous
// distinct rows differ by 1 -> stride-68 gives distinct banks. W loads: all
// lanes share k, 8 contiguous float4 (128B) -> conflict-free.
// ---------------------------------------------------------------------------
__device__ __forceinline__ void gemv_4x8(
    const float* __restrict__ sW,    // sW[k*64 + j] = W[j][k]
    const float* __restrict__ sAct,  // sAct[row*XSTR + k]
    int warp, int q, int jg,
    float acc[4][8])
{
    const int rb = warp * 16 + q;
#pragma unroll 8
    for (int k = 0; k < DIM; ++k) {
        float4 w0 = *(const float4*)&sW[k * DIM + jg];
        float4 w1 = *(const float4*)&sW[k * DIM + jg + 4];
#pragma unroll
        for (int i = 0; i < 4; ++i) {
            float xv = sAct[(rb + 4 * i) * XSTR + k];
            acc[i][0] += xv * w0.x; acc[i][1] += xv * w0.y;
            acc[i][2] += xv * w0.z; acc[i][3] += xv * w0.w;
            acc[i][4] += xv * w1.x; acc[i][5] += xv * w1.y;
            acc[i][6] += xv * w1.z; acc[i][7] += xv * w1.w;
        }
    }
}

__device__ __forceinline__ void load_w_transposed(
    const float* __restrict__ W, float* __restrict__ sW, int tid)
{
#pragma unroll
    for (int i = 0; i < (DIM * DIM) / TPB; ++i) {
        int idx = tid + i * TPB;
        int j = idx >> 6;
        int k = idx & 63;
        sW[k * DIM + j] = W[idx];
    }
}

// ---------------------------------------------------------------------------
// out[row] = x[row] @ Wr^T for all rows
// ---------------------------------------------------------------------------
__global__ __launch_bounds__(TPB) void gemm_wr_kernel(
    const float* __restrict__ x,
    const float* __restrict__ Wr,
    float* __restrict__ out)
{
    __shared__ float sW[DIM * DIM];
    __shared__ float sX[RPB * XSTR];

    const int tid = threadIdx.x;
    load_w_transposed(Wr, sW, tid);

    // load 64x64 x tile, coalesced float4, padded smem rows
    const int rowbase = blockIdx.x * RPB;
    const float4* xg = (const float4*)(x + (size_t)rowbase * DIM);
#pragma unroll
    for (int i = 0; i < (RPB * DIM / 4) / TPB; ++i) {
        int f4 = tid + i * TPB;
        int row = f4 >> 4;
        int c4 = f4 & 15;
        *(float4*)&sX[row * XSTR + c4 * 4] = xg[f4];
    }
    __syncthreads();

    const int warp = tid >> 5;
    const int lane = tid & 31;
    const int t = lane & 7;
    const int q = lane >> 3;
    const int jg = t << 3;

    float acc[4][8];
#pragma unroll
    for (int i = 0; i < 4; ++i)
#pragma unroll
        for (int j = 0; j < 8; ++j) acc[i][j] = 0.f;

    gemv_4x8(sW, sX, warp, q, jg, acc);

#pragma unroll
    for (int i = 0; i < 4; ++i) {
        int row = rowbase + warp * 16 + q + 4 * i;
        float* o = out + (size_t)row * DIM + jg;
        ((float4*)o)[0] = make_float4(acc[i][0], acc[i][1], acc[i][2], acc[i][3]);
        ((float4*)o)[1] = make_float4(acc[i][4], acc[i][5], acc[i][6], acc[i][7]);
    }
}

// ---------------------------------------------------------------------------
// Level lvl (1..7): out[p] = tanh(out[p] + (sum of 8 children) @ Wl^T + bl)
// Parent node id is analytic: dsts = repeat(arange + lvl*NPL).
// ---------------------------------------------------------------------------
__global__ __launch_bounds__(TPB) void level_kernel(
    const int* __restrict__ srcs,
    const float* __restrict__ Wl,
    const float* __restrict__ bl,
    float* __restrict__ out,
    int lvl)
{
    __shared__ float sW[DIM * DIM];
    __shared__ float sAgg[RPB * XSTR];
    __shared__ float sB[DIM];

    const int tid = threadIdx.x;
    load_w_transposed(Wl, sW, tid);
    if (tid < DIM) sB[tid] = bl[tid];

    // ---- gather: 2 threads per parent, each handles 32 dims of 8 children
    {
        const int p = tid >> 1;            // parent within block (0..63)
        const int h = tid & 1;             // half (dims [h*32, h*32+32))
        const int p_local = blockIdx.x * RPB + p;
        const long eb = (long)(lvl - 1) * EPL + (long)p_local * CPN;
        int4 s0 = *(const int4*)&srcs[eb];
        int4 s1 = *(const int4*)&srcs[eb + 4];
        int cidx[8] = {s0.x, s0.y, s0.z, s0.w, s1.x, s1.y, s1.z, s1.w};

        float g[32];
#pragma unroll
        for (int m = 0; m < 32; ++m) g[m] = 0.f;

#pragma unroll
        for (int c = 0; c < CPN; ++c) {
            const float4* cp = (const float4*)(out + (size_t)cidx[c] * DIM + h * 32);
#pragma unroll
            for (int m = 0; m < 8; ++m) {
                float4 v = cp[m];
                g[4 * m + 0] += v.x; g[4 * m + 1] += v.y;
                g[4 * m + 2] += v.z; g[4 * m + 3] += v.w;
            }
        }
        float* dst = &sAgg[p * XSTR + h * 32];
#pragma unroll
        for (int m = 0; m < 8; ++m)
            ((float4*)dst)[m] = make_float4(g[4 * m], g[4 * m + 1], g[4 * m + 2], g[4 * m + 3]);
    }
    __syncthreads();

    // ---- GEMV + epilogue
    const int warp = tid >> 5;
    const int lane = tid & 31;
    const int t = lane & 7;
    const int q = lane >> 3;
    const int jg = t << 3;

    float acc[4][8];
#pragma unroll
    for (int i = 0; i < 4; ++i)
#pragma unroll
        for (int j = 0; j < 8; ++j) acc[i][j] = 0.f;

    gemv_4x8(sW, sAgg, warp, q, jg, acc);

    float4 b0 = *(const float4*)&sB[jg];
    float4 b1 = *(const float4*)&sB[jg + 4];

#pragma unroll
    for (int i = 0; i < 4; ++i) {
        int p_node = lvl * NPL + blockIdx.x * RPB + warp * 16 + q + 4 * i;
        float* o = out + (size_t)p_node * DIM + jg;
        float4 h0 = ((const float4*)o)[0];
        float4 h1 = ((const float4*)o)[1];
        float4 r0, r1;
        r0.x = tanhf(h0.x + b0.x + acc[i][0]);
        r0.y = tanhf(h0.y + b0.y + acc[i][1]);
        r0.z = tanhf(h0.z + b0.z + acc[i][2]);
        r0.w = tanhf(h0.w + b0.w + acc[i][3]);
        r1.x = tanhf(h1.x + b1.x + acc[i][4]);
        r1.y = tanhf(h1.y + b1.y + acc[i][5]);
        r1.z = tanhf(h1.z + b1.z + acc[i][6]);
        r1.w = tanhf(h1.w + b1.w + acc[i][7]);
        ((float4*)o)[0] = r0;
        ((float4*)o)[1] = r1;
    }
}

extern "C" void kernel_launch(void* const* d_in, const int* in_sizes, int n_in,
                              void* d_out, int out_size)
{
    const float* x  = (const float*)d_in[0];
    const int*   ei = (const int*)d_in[1];
    const float* Wl = (const float*)d_in[2];
    const float* bl = (const float*)d_in[3];
    const float* Wr = (const float*)d_in[4];
    float* out = (float*)d_out;

    const int E = in_sizes[1] / 2;
    const int* srcs = ei;   // dsts (ei + E) not needed: parent ids are analytic

    gemm_wr_kernel<<<N_NODES / RPB, TPB>>>(x, Wr, out);

    for (int lvl = 1; lvl < LEVELS; ++lvl)
        level_kernel<<<NPL / RPB, TPB>>>(srcs, Wl, bl, out, lvl);
}

// round 4
// speedup vs baseline: 1.5770x; 1.3433x over previous
#include <cuda_runtime.h>

#define DIM 64
#define NPL 16384
#define CPN 8
#define LEVELS 8
#define N_NODES (LEVELS * NPL)
#define EPL (NPL * CPN)
#define XSTR 68   // activation smem row stride: rows 1 apart -> banks 4 apart

__device__ float d_WlT[DIM * DIM];   // d_WlT[k*64+j] = Wl[j][k]
__device__ float d_WrT[DIM * DIM];

__device__ __forceinline__ float tanh_fast(float x) {
    float y;
    asm("tanh.approx.f32 %0, %1;" : "=f"(y) : "f"(x));
    return y;
}

// One-time transpose of both weight matrices into global scratch.
__global__ void transpose_w_kernel(const float* __restrict__ Wl,
                                   const float* __restrict__ Wr)
{
    int idx = blockIdx.x * blockDim.x + threadIdx.x;   // 0..4095
    int j = idx >> 6, k = idx & 63;
    d_WlT[k * DIM + j] = Wl[idx];
    d_WrT[k * DIM + j] = Wr[idx];
}

// ---------------------------------------------------------------------------
// out = x @ Wr^T for all nodes.  64 rows/block, 128 threads, thread = 4r x 8c.
// ---------------------------------------------------------------------------
#define G_TPB 128
#define G_RPB 64
__global__ __launch_bounds__(G_TPB) void gemm_wr_kernel(
    const float* __restrict__ x,
    float* __restrict__ out)
{
    __shared__ float sW[DIM * DIM];       // already transposed: sW[k*64+j]
    __shared__ float sX[G_RPB * XSTR];

    const int tid = threadIdx.x;

    // coalesced copy of pre-transposed W (no conflicts)
    {
        const float4* ws = (const float4*)d_WrT;
        float4* wd = (float4*)sW;
#pragma unroll
        for (int i = 0; i < (DIM * DIM / 4) / G_TPB; ++i)
            wd[tid + i * G_TPB] = ws[tid + i * G_TPB];
    }

    const int rowbase = blockIdx.x * G_RPB;
    const float4* xg = (const float4*)(x + (size_t)rowbase * DIM);
#pragma unroll
    for (int i = 0; i < (G_RPB * DIM / 4) / G_TPB; ++i) {
        int f4 = tid + i * G_TPB;
        *(float4*)&sX[(f4 >> 4) * XSTR + (f4 & 15) * 4] = xg[f4];
    }
    __syncthreads();

    const int warp = tid >> 5, lane = tid & 31;
    const int t = lane & 7, q = lane >> 3;
    const int jg = t << 3;
    const int rb = warp * 16 + q;

    float acc[4][8];
#pragma unroll
    for (int i = 0; i < 4; ++i)
#pragma unroll
        for (int j = 0; j < 8; ++j) acc[i][j] = 0.f;

#pragma unroll 8
    for (int k = 0; k < DIM; ++k) {
        float4 w0 = *(const float4*)&sW[k * DIM + jg];
        float4 w1 = *(const float4*)&sW[k * DIM + jg + 4];
#pragma unroll
        for (int i = 0; i < 4; ++i) {
            float xv = sX[(rb + 4 * i) * XSTR + k];
            acc[i][0] += xv * w0.x; acc[i][1] += xv * w0.y;
            acc[i][2] += xv * w0.z; acc[i][3] += xv * w0.w;
            acc[i][4] += xv * w1.x; acc[i][5] += xv * w1.y;
            acc[i][6] += xv * w1.z; acc[i][7] += xv * w1.w;
        }
    }

#pragma unroll
    for (int i = 0; i < 4; ++i) {
        float* o = out + (size_t)(rowbase + rb + 4 * i) * DIM + jg;
        ((float4*)o)[0] = make_float4(acc[i][0], acc[i][1], acc[i][2], acc[i][3]);
        ((float4*)o)[1] = make_float4(acc[i][4], acc[i][5], acc[i][6], acc[i][7]);
    }
}

// ---------------------------------------------------------------------------
// Level lvl: out[p] = tanh(out[p] + (sum 8 children) @ Wl^T + bl)
// 16 parents/block, 128 threads, 1024 blocks -> high occupancy.
// ---------------------------------------------------------------------------
#define L_TPB 128
#define L_PPB 16
__global__ __launch_bounds__(L_TPB) void level_kernel(
    const int* __restrict__ srcs,
    const float* __restrict__ bl,
    float* __restrict__ out,
    int lvl)
{
    __shared__ float sW[DIM * DIM];
    __shared__ float sAgg[L_PPB * XSTR];
    __shared__ float sB[DIM];

    const int tid = threadIdx.x;
    const int p = tid >> 3;        // parent slot 0..15
    const int t = tid & 7;         // dim slice: [t*8, t*8+8)
    const int jg = t << 3;

    // prefetch child indices (int4 aligned)
    const int p_global = blockIdx.x * L_PPB + p;
    const long eb = (long)(lvl - 1) * EPL + (long)p_global * CPN;
    int4 s0 = *(const int4*)&srcs[eb];
    int4 s1 = *(const int4*)&srcs[eb + 4];

    // coalesced W copy
    {
        const float4* ws = (const float4*)d_WlT;
        float4* wd = (float4*)sW;
#pragma unroll
        for (int i = 0; i < (DIM * DIM / 4) / L_TPB; ++i)
            wd[tid + i * L_TPB] = ws[tid + i * L_TPB];
    }
    if (tid < DIM) sB[tid] = bl[tid];

    // gather-sum 8 children, this thread covers 8 dims
    float4 a0 = make_float4(0.f, 0.f, 0.f, 0.f);
    float4 a1 = make_float4(0.f, 0.f, 0.f, 0.f);
    int cidx[8] = {s0.x, s0.y, s0.z, s0.w, s1.x, s1.y, s1.z, s1.w};
#pragma unroll
    for (int c = 0; c < CPN; ++c) {
        const float4* cp = (const float4*)(out + (size_t)cidx[c] * DIM + jg);
        float4 c0 = cp[0];
        float4 c1 = cp[1];
        a0.x += c0.x; a0.y += c0.y; a0.z += c0.z; a0.w += c0.w;
        a1.x += c1.x; a1.y += c1.y; a1.z += c1.z; a1.w += c1.w;
    }
    *(float4*)&sAgg[p * XSTR + jg] = a0;
    *(float4*)&sAgg[p * XSTR + jg + 4] = a1;

    __syncthreads();

    // GEMV: thread = row p, cols [jg, jg+8)
    float acc[8];
#pragma unroll
    for (int j = 0; j < 8; ++j) acc[j] = 0.f;

    const float* ag = &sAgg[p * XSTR];
#pragma unroll 8
    for (int k = 0; k < DIM; ++k) {
        float4 w0 = *(const float4*)&sW[k * DIM + jg];
        float4 w1 = *(const float4*)&sW[k * DIM + jg + 4];
        float av = ag[k];
        acc[0] += av * w0.x; acc[1] += av * w0.y;
        acc[2] += av * w0.z; acc[3] += av * w0.w;
        acc[4] += av * w1.x; acc[5] += av * w1.y;
        acc[6] += av * w1.z; acc[7] += av * w1.w;
    }

    const int p_node = lvl * NPL + p_global;
    float* o = out + (size_t)p_node * DIM + jg;
    float4 h0 = ((const float4*)o)[0];
    float4 h1 = ((const float4*)o)[1];
    float4 b0 = *(const float4*)&sB[jg];
    float4 b1 = *(const float4*)&sB[jg + 4];

    float4 r0, r1;
    r0.x = tanh_fast(h0.x + b0.x + acc[0]);
    r0.y = tanh_fast(h0.y + b0.y + acc[1]);
    r0.z = tanh_fast(h0.z + b0.z + acc[2]);
    r0.w = tanh_fast(h0.w + b0.w + acc[3]);
    r1.x = tanh_fast(h1.x + b1.x + acc[4]);
    r1.y = tanh_fast(h1.y + b1.y + acc[5]);
    r1.z = tanh_fast(h1.z + b1.z + acc[6]);
    r1.w = tanh_fast(h1.w + b1.w + acc[7]);

    ((float4*)o)[0] = r0;
    ((float4*)o)[1] = r1;
}

extern "C" void kernel_launch(void* const* d_in, const int* in_sizes, int n_in,
                              void* d_out, int out_size)
{
    const float* x  = (const float*)d_in[0];
    const int*   ei = (const int*)d_in[1];
    const float* Wl = (const float*)d_in[2];
    const float* bl = (const float*)d_in[3];
    const float* Wr = (const float*)d_in[4];
    float* out = (float*)d_out;

    const int* srcs = ei;   // parent ids analytic; dsts unused

    transpose_w_kernel<<<16, 256>>>(Wl, Wr);
    gemm_wr_kernel<<<N_NODES / G_RPB, G_TPB>>>(x, out);
    for (int lvl = 1; lvl < LEVELS; ++lvl)
        level_kernel<<<NPL / L_PPB, L_TPB>>>(srcs, bl, out, lvl);
}

// round 5
// speedup vs baseline: 1.8109x; 1.1483x over previous
#include <cuda_runtime.h>

#define DIM 64
#define NPL 16384
#define CPN 8
#define LEVELS 8
#define N_NODES (LEVELS * NPL)
#define EPL (NPL * CPN)
#define XSTR 68          // smem activation row stride (float): rows 1 apart -> banks 4 apart

typedef unsigned long long u64;

__device__ float d_WlT[DIM * DIM];     // d_WlT[k*64+j] = Wl[j][k]
__device__ float d_WrT[DIM * DIM];
__device__ unsigned g_ctr[LEVELS];     // global barrier counters (reset each replay)

__device__ __forceinline__ float tanh_fast(float x) {
    float y;
    asm("tanh.approx.f32 %0, %1;" : "=f"(y) : "f"(x));
    return y;
}
__device__ __forceinline__ u64 pack2(float x) {
    u64 d;
    asm("mov.b64 %0, {%1, %1};" : "=l"(d) : "f"(x));
    return d;
}
__device__ __forceinline__ void fma2(u64& d, u64 a, u64 b) {
    asm("fma.rn.f32x2 %0, %1, %2, %3;" : "=l"(d) : "l"(a), "l"(b), "l"(d));
}
__device__ __forceinline__ float2 unpack2(u64 d) {
    float2 f;
    asm("mov.b64 {%0, %1}, %2;" : "=f"(f.x), "=f"(f.y) : "l"(d));
    return f;
}

// ---------------------------------------------------------------------------
// Init: transpose both W matrices into global scratch; zero barrier counters.
// ---------------------------------------------------------------------------
__global__ void init_kernel(const float* __restrict__ Wl,
                            const float* __restrict__ Wr)
{
    int idx = blockIdx.x * blockDim.x + threadIdx.x;   // 0..4095
    int j = idx >> 6, k = idx & 63;
    d_WlT[k * DIM + j] = Wl[idx];
    d_WrT[k * DIM + j] = Wr[idx];
    if (idx < LEVELS) g_ctr[idx] = 0u;
}

// ---------------------------------------------------------------------------
// out = x @ Wr^T for all nodes. 64 rows/block, 128 threads, thread = 4r x 8c,
// packed f32x2 accumulators.
// ---------------------------------------------------------------------------
#define G_TPB 128
#define G_RPB 64
__global__ __launch_bounds__(G_TPB) void gemm_wr_kernel(
    const float* __restrict__ x,
    float* __restrict__ out)
{
    __shared__ float sW[DIM * DIM];       // sW[k*64+j]
    __shared__ float sX[G_RPB * XSTR];

    const int tid = threadIdx.x;

    {   // coalesced copy of pre-transposed W
        const float4* ws = (const float4*)d_WrT;
        float4* wd = (float4*)sW;
#pragma unroll
        for (int i = 0; i < (DIM * DIM / 4) / G_TPB; ++i)
            wd[tid + i * G_TPB] = ws[tid + i * G_TPB];
    }

    const int rowbase = blockIdx.x * G_RPB;
    const float4* xg = (const float4*)(x + (size_t)rowbase * DIM);
#pragma unroll
    for (int i = 0; i < (G_RPB * DIM / 4) / G_TPB; ++i) {
        int f4 = tid + i * G_TPB;
        *(float4*)&sX[(f4 >> 4) * XSTR + (f4 & 15) * 4] = xg[f4];
    }
    __syncthreads();

    const int warp = tid >> 5, lane = tid & 31;
    const int t = lane & 7, q = lane >> 3;
    const int jg = t << 3;
    const int rb = warp * 16 + q;

    u64 acc[4][4];
#pragma unroll
    for (int i = 0; i < 4; ++i)
#pragma unroll
        for (int j = 0; j < 4; ++j) acc[i][j] = 0ull;

#pragma unroll 8
    for (int k = 0; k < DIM; ++k) {
        ulonglong2 wa = *(const ulonglong2*)&sW[k * DIM + jg];
        ulonglong2 wb = *(const ulonglong2*)&sW[k * DIM + jg + 4];
#pragma unroll
        for (int i = 0; i < 4; ++i) {
            u64 xp = pack2(sX[(rb + 4 * i) * XSTR + k]);
            fma2(acc[i][0], xp, wa.x);
            fma2(acc[i][1], xp, wa.y);
            fma2(acc[i][2], xp, wb.x);
            fma2(acc[i][3], xp, wb.y);
        }
    }

#pragma unroll
    for (int i = 0; i < 4; ++i) {
        float2 f0 = unpack2(acc[i][0]);
        float2 f1 = unpack2(acc[i][1]);
        float2 f2 = unpack2(acc[i][2]);
        float2 f3 = unpack2(acc[i][3]);
        float* o = out + (size_t)(rowbase + rb + 4 * i) * DIM + jg;
        ((float4*)o)[0] = make_float4(f0.x, f0.y, f1.x, f1.y);
        ((float4*)o)[1] = make_float4(f2.x, f2.y, f3.x, f3.y);
    }
}

// ---------------------------------------------------------------------------
// Persistent levels kernel: one launch handles lvl = 1..7 with a global
// barrier between levels. 256 blocks x 128 threads, 64 parents/block.
// All blocks co-resident (occ >= 2), so the spin barrier cannot deadlock.
// ---------------------------------------------------------------------------
#define L_TPB 128
#define L_GRID 256
#define PPB 64
__global__ __launch_bounds__(L_TPB, 2) void levels_kernel(
    const int* __restrict__ srcs,
    const float* __restrict__ bl,
    float* __restrict__ out)
{
    __shared__ float sW[DIM * DIM];
    __shared__ float sAgg[PPB * XSTR];
    __shared__ float sB[DIM];

    const int tid = threadIdx.x;
    const int blk = blockIdx.x;

    {   // W + bias loaded ONCE for all 7 levels
        const float4* ws = (const float4*)d_WlT;
        float4* wd = (float4*)sW;
#pragma unroll
        for (int i = 0; i < (DIM * DIM / 4) / L_TPB; ++i)
            wd[tid + i * L_TPB] = ws[tid + i * L_TPB];
        if (tid < DIM) sB[tid] = bl[tid];
    }
    __syncthreads();

    const int warp = tid >> 5, lane = tid & 31;
    const int t = lane & 7, q = lane >> 3;
    const int jg = t << 3;
    const int rb = warp * 16 + q;          // 0..51 (+12 max -> 63)

    const int gp = tid >> 1;               // gather: parent slot 0..63
    const int gh = tid & 1;                // gather: half (dims gh*32..+32)

    for (int lvl = 1; lvl < LEVELS; ++lvl) {
        // ---- gather: 2 threads per parent, 32 dims x 8 children each
        {
            const int p_global = blk * PPB + gp;
            const long eb = (long)(lvl - 1) * EPL + (long)p_global * CPN;
            int4 s0 = *(const int4*)&srcs[eb];
            int4 s1 = *(const int4*)&srcs[eb + 4];
            int cidx[8] = {s0.x, s0.y, s0.z, s0.w, s1.x, s1.y, s1.z, s1.w};

            float4 g[8];
#pragma unroll
            for (int m = 0; m < 8; ++m) g[m] = make_float4(0.f, 0.f, 0.f, 0.f);
#pragma unroll
            for (int c = 0; c < CPN; ++c) {
                const float4* cp = (const float4*)(out + (size_t)cidx[c] * DIM + gh * 32);
#pragma unroll
                for (int m = 0; m < 8; ++m) {
                    float4 v = cp[m];
                    g[m].x += v.x; g[m].y += v.y; g[m].z += v.z; g[m].w += v.w;
                }
            }
            float4* dst = (float4*)&sAgg[gp * XSTR + gh * 32];
#pragma unroll
            for (int m = 0; m < 8; ++m) dst[m] = g[m];
        }
        __syncthreads();

        // ---- GEMV: thread = 4 parents x 8 cols, f32x2 accumulators
        u64 acc[4][4];
#pragma unroll
        for (int i = 0; i < 4; ++i)
#pragma unroll
            for (int j = 0; j < 4; ++j) acc[i][j] = 0ull;

#pragma unroll 8
        for (int k = 0; k < DIM; ++k) {
            ulonglong2 wa = *(const ulonglong2*)&sW[k * DIM + jg];
            ulonglong2 wb = *(const ulonglong2*)&sW[k * DIM + jg + 4];
#pragma unroll
            for (int i = 0; i < 4; ++i) {
                u64 xp = pack2(sAgg[(rb + 4 * i) * XSTR + k]);
                fma2(acc[i][0], xp, wa.x);
                fma2(acc[i][1], xp, wa.y);
                fma2(acc[i][2], xp, wb.x);
                fma2(acc[i][3], xp, wb.y);
            }
        }

        float4 b0 = *(const float4*)&sB[jg];
        float4 b1 = *(const float4*)&sB[jg + 4];

#pragma unroll
        for (int i = 0; i < 4; ++i) {
            const int p_node = lvl * NPL + blk * PPB + rb + 4 * i;
            float* o = out + (size_t)p_node * DIM + jg;
            float4 h0 = ((const float4*)o)[0];
            float4 h1 = ((const float4*)o)[1];
            float2 f0 = unpack2(acc[i][0]);
            float2 f1 = unpack2(acc[i][1]);
            float2 f2 = unpack2(acc[i][2]);
            float2 f3 = unpack2(acc[i][3]);
            float4 r0, r1;
            r0.x = tanh_fast(h0.x + b0.x + f0.x);
            r0.y = tanh_fast(h0.y + b0.y + f0.y);
            r0.z = tanh_fast(h0.z + b0.z + f1.x);
            r0.w = tanh_fast(h0.w + b0.w + f1.y);
            r1.x = tanh_fast(h1.x + b1.x + f2.x);
            r1.y = tanh_fast(h1.y + b1.y + f2.y);
            r1.z = tanh_fast(h1.z + b1.z + f3.x);
            r1.w = tanh_fast(h1.w + b1.w + f3.y);
            ((float4*)o)[0] = r0;
            ((float4*)o)[1] = r1;
        }

        // ---- global barrier before next level
        __syncthreads();
        __threadfence();
        if (tid == 0) {
            atomicAdd(&g_ctr[lvl], 1u);
            while (((volatile unsigned*)g_ctr)[lvl] < L_GRID) __nanosleep(64);
        }
        __syncthreads();
    }
}

extern "C" void kernel_launch(void* const* d_in, const int* in_sizes, int n_in,
                              void* d_out, int out_size)
{
    const float* x  = (const float*)d_in[0];
    const int*   ei = (const int*)d_in[1];
    const float* Wl = (const float*)d_in[2];
    const float* bl = (const float*)d_in[3];
    const float* Wr = (const float*)d_in[4];
    float* out = (float*)d_out;

    const int* srcs = ei;   // parent ids are analytic; dsts unused

    init_kernel<<<16, 256>>>(Wl, Wr);
    gemm_wr_kernel<<<N_NODES / G_RPB, G_TPB>>>(x, out);
    levels_kernel<<<L_GRID, L_TPB>>>(srcs, bl, out);
}

// round 6
// speedup vs baseline: 1.8818x; 1.0392x over previous
#include <cuda_runtime.h>

#define DIM 64
#define NPL 16384
#define CPN 8
#define LEVELS 8
#define N_NODES (LEVELS * NPL)
#define EPL (NPL * CPN)
#define XSTR 68          // smem activation row stride (floats)

typedef unsigned long long u64;

__device__ float d_WlT[DIM * DIM];     // d_WlT[k*64+j] = Wl[j][k]
__device__ float d_WrT[DIM * DIM];
__device__ unsigned g_ctr[LEVELS];     // global barrier counters (reset each replay)

__device__ __forceinline__ float tanh_fast(float x) {
    float y;
    asm("tanh.approx.f32 %0, %1;" : "=f"(y) : "f"(x));
    return y;
}
__device__ __forceinline__ u64 pack2(float x) {
    u64 d;
    asm("mov.b64 %0, {%1, %1};" : "=l"(d) : "f"(x));
    return d;
}
__device__ __forceinline__ void fma2(u64& d, u64 a, u64 b) {
    asm("fma.rn.f32x2 %0, %1, %2, %3;" : "=l"(d) : "l"(a), "l"(b), "l"(d));
}
__device__ __forceinline__ float2 unpack2(u64 d) {
    float2 f;
    asm("mov.b64 {%0, %1}, %2;" : "=f"(f.x), "=f"(f.y) : "l"(d));
    return f;
}

// ---------------------------------------------------------------------------
// Init: transpose both W matrices; zero barrier counters.
// ---------------------------------------------------------------------------
__global__ void init_kernel(const float* __restrict__ Wl,
                            const float* __restrict__ Wr)
{
    int idx = blockIdx.x * blockDim.x + threadIdx.x;   // 0..4095
    int j = idx >> 6, k = idx & 63;
    d_WlT[k * DIM + j] = Wl[idx];
    d_WrT[k * DIM + j] = Wr[idx];
    if (idx < LEVELS) g_ctr[idx] = 0u;
}

// ---------------------------------------------------------------------------
// out = x @ Wr^T for all nodes. 64 rows/block, 128 threads, 4r x 8c, f32x2.
// ---------------------------------------------------------------------------
#define G_TPB 128
#define G_RPB 64
__global__ __launch_bounds__(G_TPB) void gemm_wr_kernel(
    const float* __restrict__ x,
    float* __restrict__ out)
{
    __shared__ float sW[DIM * DIM];
    __shared__ float sX[G_RPB * XSTR];

    const int tid = threadIdx.x;
    {
        const float4* ws = (const float4*)d_WrT;
        float4* wd = (float4*)sW;
#pragma unroll
        for (int i = 0; i < (DIM * DIM / 4) / G_TPB; ++i)
            wd[tid + i * G_TPB] = ws[tid + i * G_TPB];
    }
    const int rowbase = blockIdx.x * G_RPB;
    const float4* xg = (const float4*)(x + (size_t)rowbase * DIM);
#pragma unroll
    for (int i = 0; i < (G_RPB * DIM / 4) / G_TPB; ++i) {
        int f4 = tid + i * G_TPB;
        *(float4*)&sX[(f4 >> 4) * XSTR + (f4 & 15) * 4] = xg[f4];
    }
    __syncthreads();

    const int warp = tid >> 5, lane = tid & 31;
    const int t = lane & 7, q = lane >> 3;
    const int jg = t << 3;
    const int rb = warp * 16 + q;

    u64 acc[4][4];
#pragma unroll
    for (int i = 0; i < 4; ++i)
#pragma unroll
        for (int j = 0; j < 4; ++j) acc[i][j] = 0ull;

#pragma unroll 8
    for (int k = 0; k < DIM; ++k) {
        ulonglong2 wa = *(const ulonglong2*)&sW[k * DIM + jg];
        ulonglong2 wb = *(const ulonglong2*)&sW[k * DIM + jg + 4];
#pragma unroll
        for (int i = 0; i < 4; ++i) {
            u64 xp = pack2(sX[(rb + 4 * i) * XSTR + k]);
            fma2(acc[i][0], xp, wa.x);
            fma2(acc[i][1], xp, wa.y);
            fma2(acc[i][2], xp, wb.x);
            fma2(acc[i][3], xp, wb.y);
        }
    }
#pragma unroll
    for (int i = 0; i < 4; ++i) {
        float2 f0 = unpack2(acc[i][0]);
        float2 f1 = unpack2(acc[i][1]);
        float2 f2 = unpack2(acc[i][2]);
        float2 f3 = unpack2(acc[i][3]);
        float* o = out + (size_t)(rowbase + rb + 4 * i) * DIM + jg;
        ((float4*)o)[0] = make_float4(f0.x, f0.y, f1.x, f1.y);
        ((float4*)o)[1] = make_float4(f2.x, f2.y, f3.x, f3.y);
    }
}

// ---------------------------------------------------------------------------
// Persistent levels kernel: lvl = 1..7 with global barriers.
// 512 blocks x 128 threads, occ 4 (16 warps/SM), 32 parents/block.
// All levels' child indices preloaded to smem; H prefetched before gather.
// ---------------------------------------------------------------------------
#define L_TPB 128
#define L_GRID 512
#define PPB 32
__global__ __launch_bounds__(L_TPB, 4) void levels_kernel(
    const int* __restrict__ srcs,
    const float* __restrict__ bl,
    float* __restrict__ out)
{
    __shared__ float sW[DIM * DIM];
    __shared__ float sAgg[PPB * XSTR];
    __shared__ int   sIdx[(LEVELS - 1) * PPB * CPN];   // [lvl][p][c]
    __shared__ float sB[DIM];

    const int tid = threadIdx.x;
    const int blk = blockIdx.x;

    // ---- one-time: W, bias, all child indices
    {
        const float4* ws = (const float4*)d_WlT;
        float4* wd = (float4*)sW;
#pragma unroll
        for (int i = 0; i < (DIM * DIM / 4) / L_TPB; ++i)
            wd[tid + i * L_TPB] = ws[tid + i * L_TPB];
        if (tid < DIM) sB[tid] = bl[tid];

        // 7 levels * 32 parents * 8 children = 1792 ints = 448 int4
        const int4* sg = (const int4*)srcs;
        int4* sd = (int4*)sIdx;
#pragma unroll
        for (int i = 0; i < 4; ++i) {
            int j = tid + i * L_TPB;
            if (j < (LEVELS - 1) * PPB * 2) {
                int lvl0 = j >> 6;          // 0..6
                int rem = j & 63;           // p*2 + h
                sd[j] = sg[lvl0 * (EPL / 4) + ((size_t)blk * PPB + (rem >> 1)) * 2 + (rem & 1)];
            }
        }
    }
    __syncthreads();

    // GEMV/epilogue mapping: thread = 2 parents x 8 cols
    const int warp = tid >> 5, lane = tid & 31;
    const int t = lane & 7, q = lane >> 3;
    const int jg = t << 3;
    const int pr0 = warp * 8 + q;          // parent slot A (0..31)
    const int pr1 = pr0 + 4;               // parent slot B

    // gather mapping: 4 threads per parent
    const int gp = tid >> 2;               // parent slot 0..31
    const int gq = tid & 3;                // dim quarter: [gq*16, gq*16+16)

    for (int lvl = 1; lvl < LEVELS; ++lvl) {
        // ---- prefetch H rows (independent of gather; overlaps LDG latency)
        const size_t pn0 = (size_t)(lvl * NPL + blk * PPB + pr0) * DIM + jg;
        const size_t pn1 = (size_t)(lvl * NPL + blk * PPB + pr1) * DIM + jg;
        float4 hA0 = ((const float4*)(out + pn0))[0];
        float4 hA1 = ((const float4*)(out + pn0))[1];
        float4 hB0 = ((const float4*)(out + pn1))[0];
        float4 hB1 = ((const float4*)(out + pn1))[1];

        // ---- gather: each thread sums 16 dims of 8 children
        {
            const int* ip = &sIdx[((lvl - 1) * PPB + gp) * CPN];
            int c0 = ip[0], c1 = ip[1], c2 = ip[2], c3 = ip[3];
            int c4 = ip[4], c5 = ip[5], c6 = ip[6], c7 = ip[7];
            int cidx[8] = {c0, c1, c2, c3, c4, c5, c6, c7};

            float4 g[4];
#pragma unroll
            for (int m = 0; m < 4; ++m) g[m] = make_float4(0.f, 0.f, 0.f, 0.f);
#pragma unroll
            for (int c = 0; c < CPN; ++c) {
                const float4* cp = (const float4*)(out + (size_t)cidx[c] * DIM + gq * 16);
#pragma unroll
                for (int m = 0; m < 4; ++m) {
                    float4 v = cp[m];
                    g[m].x += v.x; g[m].y += v.y; g[m].z += v.z; g[m].w += v.w;
                }
            }
            float4* dst = (float4*)&sAgg[gp * XSTR + gq * 16];
#pragma unroll
            for (int m = 0; m < 4; ++m) dst[m] = g[m];
        }
        __syncthreads();

        // ---- GEMV: 2 parents x 8 cols, f32x2
        u64 acc[2][4];
#pragma unroll
        for (int i = 0; i < 2; ++i)
#pragma unroll
            for (int j = 0; j < 4; ++j) acc[i][j] = 0ull;

#pragma unroll 8
        for (int k = 0; k < DIM; ++k) {
            ulonglong2 wa = *(const ulonglong2*)&sW[k * DIM + jg];
            ulonglong2 wb = *(const ulonglong2*)&sW[k * DIM + jg + 4];
            u64 x0 = pack2(sAgg[pr0 * XSTR + k]);
            u64 x1 = pack2(sAgg[pr1 * XSTR + k]);
            fma2(acc[0][0], x0, wa.x);
            fma2(acc[0][1], x0, wa.y);
            fma2(acc[0][2], x0, wb.x);
            fma2(acc[0][3], x0, wb.y);
            fma2(acc[1][0], x1, wa.x);
            fma2(acc[1][1], x1, wa.y);
            fma2(acc[1][2], x1, wb.x);
            fma2(acc[1][3], x1, wb.y);
        }

        float4 b0 = *(const float4*)&sB[jg];
        float4 b1 = *(const float4*)&sB[jg + 4];

        {
            float2 f0 = unpack2(acc[0][0]);
            float2 f1 = unpack2(acc[0][1]);
            float2 f2 = unpack2(acc[0][2]);
            float2 f3 = unpack2(acc[0][3]);
            float4 r0, r1;
            r0.x = tanh_fast(hA0.x + b0.x + f0.x);
            r0.y = tanh_fast(hA0.y + b0.y + f0.y);
            r0.z = tanh_fast(hA0.z + b0.z + f1.x);
            r0.w = tanh_fast(hA0.w + b0.w + f1.y);
            r1.x = tanh_fast(hA1.x + b1.x + f2.x);
            r1.y = tanh_fast(hA1.y + b1.y + f2.y);
            r1.z = tanh_fast(hA1.z + b1.z + f3.x);
            r1.w = tanh_fast(hA1.w + b1.w + f3.y);
            ((float4*)(out + pn0))[0] = r0;
            ((float4*)(out + pn0))[1] = r1;
        }
        {
            float2 f0 = unpack2(acc[1][0]);
            float2 f1 = unpack2(acc[1][1]);
            float2 f2 = unpack2(acc[1][2]);
            float2 f3 = unpack2(acc[1][3]);
            float4 r0, r1;
            r0.x = tanh_fast(hB0.x + b0.x + f0.x);
            r0.y = tanh_fast(hB0.y + b0.y + f0.y);
            r0.z = tanh_fast(hB0.z + b0.z + f1.x);
            r0.w = tanh_fast(hB0.w + b0.w + f1.y);
            r1.x = tanh_fast(hB1.x + b1.x + f2.x);
            r1.y = tanh_fast(hB1.y + b1.y + f2.y);
            r1.z = tanh_fast(hB1.z + b1.z + f3.x);
            r1.w = tanh_fast(hB1.w + b1.w + f3.y);
            ((float4*)(out + pn1))[0] = r0;
            ((float4*)(out + pn1))[1] = r1;
        }

        // ---- global barrier before next level
        __syncthreads();
        __threadfence();
        if (tid == 0) {
            atomicAdd(&g_ctr[lvl], 1u);
            while (((volatile unsigned*)g_ctr)[lvl] < L_GRID) __nanosleep(32);
        }
        __syncthreads();
    }
}

extern "C" void kernel_launch(void* const* d_in, const int* in_sizes, int n_in,
                              void* d_out, int out_size)
{
    const float* x  = (const float*)d_in[0];
    const int*   ei = (const int*)d_in[1];
    const float* Wl = (const float*)d_in[2];
    const float* bl = (const float*)d_in[3];
    const float* Wr = (const float*)d_in[4];
    float* out = (float*)d_out;

    const int* srcs = ei;   // parent ids analytic; dsts unused

    init_kernel<<<16, 256>>>(Wl, Wr);
    gemm_wr_kernel<<<N_NODES / G_RPB, G_TPB>>>(x, out);
    levels_kernel<<<L_GRID, L_TPB>>>(srcs, bl, out);
}

// round 8
// speedup vs baseline: 2.0815x; 1.1061x over previous
#include <cuda_runtime.h>

#define DIM 64
#define NPL 16384
#define CPN 8
#define LEVELS 8
#define EPL (NPL * CPN)
#define TPB 128
#define GRID 512
#define PPB 32

typedef unsigned long long u64;

__device__ unsigned g_ctr[LEVELS + 2];   // [0] leaves, [1..7] levels, [8] done/reset

__device__ __forceinline__ float tanh_fast(float x) {
    float y;
    asm("tanh.approx.f32 %0, %1;" : "=f"(y) : "f"(x));
    return y;
}
__device__ __forceinline__ u64 pack2(float x) {
    u64 d;
    asm("mov.b64 %0, {%1, %1};" : "=l"(d) : "f"(x));
    return d;
}
__device__ __forceinline__ void fma2(u64& d, u64 a, u64 b) {
    asm("fma.rn.f32x2 %0, %1, %2, %3;" : "=l"(d) : "l"(a), "l"(b), "l"(d));
}
__device__ __forceinline__ float2 unpack2(u64 d) {
    float2 f;
    asm("mov.b64 {%0, %1}, %2;" : "=f"(f.x), "=f"(f.y) : "l"(d));
    return f;
}

__device__ __forceinline__ void grid_bar(int i, int tid) {
    __syncthreads();
    __threadfence();
    if (tid == 0) {
        atomicAdd(&g_ctr[i], 1u);
        while (((volatile unsigned*)g_ctr)[i] < GRID) __nanosleep(32);
    }
    __syncthreads();
}

__global__ __launch_bounds__(TPB, 4) void dagprop_kernel(
    const float* __restrict__ x,
    const int* __restrict__ srcs,
    const float* __restrict__ Wl,
    const float* __restrict__ bl,
    const float* __restrict__ Wr,
    float* __restrict__ out)
{
    // 48KB static smem exactly: transposed weights + rotated activation tiles
    __shared__ float sWl[DIM * DIM];   // sWl[k*64 + j] = Wl[j][k]
    __shared__ float sWr[DIM * DIM];
    __shared__ float sXp[PPB * DIM];   // parent x rows, quad-rotated
    __shared__ float sAgg[PPB * DIM];  // child sums, quad-rotated

    const int tid = threadIdx.x;
    const int blk = blockIdx.x;

    // ---- prologue: transpose both W into smem (one-time; STS conflicts ok)
    {
        const float4* wl4 = (const float4*)Wl;
        const float4* wr4 = (const float4*)Wr;
#pragma unroll
        for (int i = 0; i < 8; ++i) {
            int idx4 = tid + i * TPB;        // 0..1023
            int j = idx4 >> 4;               // W row (output col) 0..63
            int kq = (idx4 & 15) << 2;       // k quad base
            float4 a = wl4[idx4];
            sWl[(kq + 0) * DIM + j] = a.x; sWl[(kq + 1) * DIM + j] = a.y;
            sWl[(kq + 2) * DIM + j] = a.z; sWl[(kq + 3) * DIM + j] = a.w;
            float4 b = wr4[idx4];
            sWr[(kq + 0) * DIM + j] = b.x; sWr[(kq + 1) * DIM + j] = b.y;
            sWr[(kq + 2) * DIM + j] = b.z; sWr[(kq + 3) * DIM + j] = b.w;
        }
    }

    const int warp = tid >> 5, lane = tid & 31;
    const int t = lane & 7, q = lane >> 3;
    const int jga = t << 2;            // cols [jga, jga+4)
    const int jgb = 32 + (t << 2);     // cols [jgb, jgb+4)
    const int pr0 = warp * 8 + q;      // row A (0..31)
    const int pr1 = pr0 + 4;           // row B
    const int rc0 = (pr0 << 2) & 63;   // per-row rotation constants
    const int rc1 = (pr1 << 2) & 63;

    const float4 bA = *(const float4*)&bl[jga];
    const float4 bB = *(const float4*)&bl[jgb];

    const int gp = tid >> 2;           // gather: parent slot 0..31
    const int gq = tid & 3;            // gather: quarter [gq*16, +16)
    const int grc = (gp << 2) & 63;

    // ---- leaves: out[r] = x[r] @ WrT for rows [blk*32, +32)
    {
        const float4* xg = (const float4*)(x + (size_t)blk * PPB * DIM);
#pragma unroll
        for (int i = 0; i < 4; ++i) {
            int f4 = tid + i * TPB;
            int row = f4 >> 4;
            int cq = (f4 & 15) << 2;
            *(float4*)&sXp[row * DIM + ((cq + (row << 2)) & 63)] = xg[f4];
        }
        __syncthreads();

        u64 acc[2][4];
#pragma unroll
        for (int i = 0; i < 2; ++i)
#pragma unroll
            for (int j = 0; j < 4; ++j) acc[i][j] = 0ull;

#pragma unroll 8
        for (int k = 0; k < DIM; ++k) {
            ulonglong2 wA = *(const ulonglong2*)&sWr[k * DIM + jga];
            ulonglong2 wB = *(const ulonglong2*)&sWr[k * DIM + jgb];
            u64 x0 = pack2(sXp[pr0 * DIM + ((k + rc0) & 63)]);
            u64 x1 = pack2(sXp[pr1 * DIM + ((k + rc1) & 63)]);
            fma2(acc[0][0], x0, wA.x); fma2(acc[0][1], x0, wA.y);
            fma2(acc[0][2], x0, wB.x); fma2(acc[0][3], x0, wB.y);
            fma2(acc[1][0], x1, wA.x); fma2(acc[1][1], x1, wA.y);
            fma2(acc[1][2], x1, wB.x); fma2(acc[1][3], x1, wB.y);
        }
#pragma unroll
        for (int i = 0; i < 2; ++i) {
            int row = blk * PPB + (i ? pr1 : pr0);
            float2 f0 = unpack2(acc[i][0]), f1 = unpack2(acc[i][1]);
            float2 f2 = unpack2(acc[i][2]), f3 = unpack2(acc[i][3]);
            float* o = out + (size_t)row * DIM;
            *(float4*)&o[jga] = make_float4(f0.x, f0.y, f1.x, f1.y);
            *(float4*)&o[jgb] = make_float4(f2.x, f2.y, f3.x, f3.y);
        }
    }
    grid_bar(0, tid);

    // ---- levels 1..7
    for (int lvl = 1; lvl < LEVELS; ++lvl) {
        // load this block's parent x rows (contiguous)
        {
            const float4* xg = (const float4*)(x + ((size_t)lvl * NPL + blk * PPB) * DIM);
#pragma unroll
            for (int i = 0; i < 4; ++i) {
                int f4 = tid + i * TPB;
                int row = f4 >> 4;
                int cq = (f4 & 15) << 2;
                *(float4*)&sXp[row * DIM + ((cq + (row << 2)) & 63)] = xg[f4];
            }
        }
        // gather: 4 threads/parent, 16 dims each, 8 children
        {
            const size_t eb = (size_t)(lvl - 1) * EPL + ((size_t)blk * PPB + gp) * CPN;
            int4 s0 = *(const int4*)&srcs[eb];
            int4 s1 = *(const int4*)&srcs[eb + 4];
            int cid[8] = {s0.x, s0.y, s0.z, s0.w, s1.x, s1.y, s1.z, s1.w};

            float4 g[4];
#pragma unroll
            for (int m = 0; m < 4; ++m) g[m] = make_float4(0.f, 0.f, 0.f, 0.f);
#pragma unroll
            for (int c = 0; c < CPN; ++c) {
                const float4* cp = (const float4*)(out + (size_t)cid[c] * DIM + (gq << 4));
#pragma unroll
                for (int m = 0; m < 4; ++m) {
                    float4 v = cp[m];
                    g[m].x += v.x; g[m].y += v.y; g[m].z += v.z; g[m].w += v.w;
                }
            }
#pragma unroll
            for (int m = 0; m < 4; ++m)
                *(float4*)&sAgg[gp * DIM + (((gq << 4) + (m << 2) + grc) & 63)] = g[m];
        }
        __syncthreads();

        // combined GEMV: acc = agg@WlT + xp@WrT
        u64 acc[2][4];
#pragma unroll
        for (int i = 0; i < 2; ++i)
#pragma unroll
            for (int j = 0; j < 4; ++j) acc[i][j] = 0ull;

#pragma unroll 8
        for (int k = 0; k < DIM; ++k) {
            ulonglong2 wlA = *(const ulonglong2*)&sWl[k * DIM + jga];
            ulonglong2 wlB = *(const ulonglong2*)&sWl[k * DIM + jgb];
            ulonglong2 wrA = *(const ulonglong2*)&sWr[k * DIM + jga];
            ulonglong2 wrB = *(const ulonglong2*)&sWr[k * DIM + jgb];
            int rk0 = (k + rc0) & 63;
            int rk1 = (k + rc1) & 63;
            u64 xa0 = pack2(sAgg[pr0 * DIM + rk0]);
            u64 xa1 = pack2(sAgg[pr1 * DIM + rk1]);
            u64 xp0 = pack2(sXp[pr0 * DIM + rk0]);
            u64 xp1 = pack2(sXp[pr1 * DIM + rk1]);
            fma2(acc[0][0], xa0, wlA.x); fma2(acc[0][1], xa0, wlA.y);
            fma2(acc[0][2], xa0, wlB.x); fma2(acc[0][3], xa0, wlB.y);
            fma2(acc[1][0], xa1, wlA.x); fma2(acc[1][1], xa1, wlA.y);
            fma2(acc[1][2], xa1, wlB.x); fma2(acc[1][3], xa1, wlB.y);
            fma2(acc[0][0], xp0, wrA.x); fma2(acc[0][1], xp0, wrA.y);
            fma2(acc[0][2], xp0, wrB.x); fma2(acc[0][3], xp0, wrB.y);
            fma2(acc[1][0], xp1, wrA.x); fma2(acc[1][1], xp1, wrA.y);
            fma2(acc[1][2], xp1, wrB.x); fma2(acc[1][3], xp1, wrB.y);
        }

        // epilogue: out[p] = tanh(acc + b)
#pragma unroll
        for (int i = 0; i < 2; ++i) {
            int row = lvl * NPL + blk * PPB + (i ? pr1 : pr0);
            float2 f0 = unpack2(acc[i][0]), f1 = unpack2(acc[i][1]);
            float2 f2 = unpack2(acc[i][2]), f3 = unpack2(acc[i][3]);
            float* o = out + (size_t)row * DIM;
            float4 rA, rB;
            rA.x = tanh_fast(f0.x + bA.x);
            rA.y = tanh_fast(f0.y + bA.y);
            rA.z = tanh_fast(f1.x + bA.z);
            rA.w = tanh_fast(f1.y + bA.w);
            rB.x = tanh_fast(f2.x + bB.x);
            rB.y = tanh_fast(f2.y + bB.y);
            rB.z = tanh_fast(f3.x + bB.z);
            rB.w = tanh_fast(f3.y + bB.w);
            *(float4*)&o[jga] = rA;
            *(float4*)&o[jgb] = rB;
        }
        grid_bar(lvl, tid);
    }

    // ---- self-reset of barrier counters (deterministic across graph replays)
    if (tid == 0) {
        unsigned old = atomicAdd(&g_ctr[LEVELS], 1u);   // index 8 = done
        if (old == GRID - 1) {
#pragma unroll
            for (int i = 0; i < LEVELS + 2; ++i)
                ((volatile unsigned*)g_ctr)[i] = 0u;
            __threadfence();
        }
    }
}

extern "C" void kernel_launch(void* const* d_in, const int* in_sizes, int n_in,
                              void* d_out, int out_size)
{
    const float* x  = (const float*)d_in[0];
    const int*   ei = (const int*)d_in[1];
    const float* Wl = (const float*)d_in[2];
    const float* bl = (const float*)d_in[3];
    const float* Wr = (const float*)d_in[4];
    float* out = (float*)d_out;

    const int* srcs = ei;   // parent ids analytic; dsts (ei + E) unused

    dagprop_kernel<<<GRID, TPB>>>(x, srcs, Wl, bl, Wr, out);
}